// round 2
// baseline (speedup 1.0000x reference)
#include <cuda_runtime.h>
#include <math.h>

#define BB   256
#define LSEQ 1800
#define FF   50
#define EE   4
#define HH   32
#define DD   64
#define G3   96      // 3*H
#define HU   32

// ---------------- device scratch (no runtime allocation allowed) ----------
__device__ float g_Wc[EE * G3 * FF];   // Wih0 @ W_in  (per expert, 96 x 50)
__device__ int   g_pair_e[2 * BB];     // routed expert per (batch, slot)
__device__ float g_pair_w[2 * BB];     // softmax weight per (batch, slot)
__device__ float g_pred[2 * BB];       // expert prediction per pair

// ---------------- prep: combined input weights Wc = Wih0 @ W_in -----------
__global__ void prep_Wc(const float* __restrict__ Wih0,
                        const float* __restrict__ W_in) {
    int e = blockIdx.x;          // 0..3
    int j = threadIdx.x;         // 0..95
    float wr[DD];
    const float* src = Wih0 + (size_t)(e * G3 + j) * DD;
#pragma unroll
    for (int d = 0; d < DD; ++d) wr[d] = src[d];
    float* dst = g_Wc + (size_t)(e * G3 + j) * FF;
    for (int f = 0; f < FF; ++f) {
        float s = 0.f;
#pragma unroll
        for (int d = 0; d < DD; ++d) s = fmaf(wr[d], __ldg(W_in + d * FF + f), s);
        dst[f] = s;
    }
}

// ---------------- prep: gating (top-2 of 4, softmax over top-2) -----------
__global__ void prep_route(const int* __restrict__ horizon,
                           const float* __restrict__ emb,
                           const float* __restrict__ W_gate,
                           const float* __restrict__ b_gate) {
    int b = threadIdx.x;         // 0..255
    int hb = horizon[b];
    const float* he = emb + (size_t)hb * DD;
    float lg[EE];
#pragma unroll
    for (int e = 0; e < EE; ++e) {
        float s = b_gate[e];
        const float* w = W_gate + e * DD;
#pragma unroll
        for (int d = 0; d < DD; ++d) s = fmaf(w[d], he[d], s);
        lg[e] = s;
    }
    // top-2 with jax.lax.top_k tie-breaking (stable: lower index first)
    int m1 = 0;
#pragma unroll
    for (int e = 1; e < EE; ++e) if (lg[e] > lg[m1]) m1 = e;
    int m2 = -1;
#pragma unroll
    for (int e = 0; e < EE; ++e) {
        if (e == m1) continue;
        if (m2 < 0 || lg[e] > lg[m2]) m2 = e;
    }
    float e2  = expf(lg[m2] - lg[m1]);     // <= 1
    float inv = 1.f / (1.f + e2);
    g_pair_e[2 * b]     = m1;
    g_pair_e[2 * b + 1] = m2;
    g_pair_w[2 * b]     = inv;             // weight of top-1
    g_pair_w[2 * b + 1] = e2 * inv;        // weight of top-2
}

__device__ __forceinline__ float sigm(float x) { return 1.f / (1.f + expf(-x)); }

// ---------------- main: fused 2-layer GRU scan per (batch, slot) pair -----
// 512 blocks x 192 threads.
//   warps 0-2 (tid 0..95):   layer-0 gate rows (step t)
//   warps 3-5 (tid 96..191): layer-1 gate rows (step t-1, pipelined)
__global__ void __launch_bounds__(192, 3) moe_gru_scan(
    const float* __restrict__ x,
    const int*   __restrict__ horizon,
    const float* __restrict__ b_in,
    const float* __restrict__ emb,
    const float* __restrict__ Wih0,  const float* __restrict__ Whh0,
    const float* __restrict__ bih0,  const float* __restrict__ bhh0,
    const float* __restrict__ Wih1,  const float* __restrict__ Whh1,
    const float* __restrict__ bih1,  const float* __restrict__ bhh1,
    const float* __restrict__ Wh1,   const float* __restrict__ bh1,
    const float* __restrict__ Wh2,   const float* __restrict__ bh2)
{
    __shared__ float sA0[G3], sG0[G3], sA1[G3], sG1[G3];
    __shared__ __align__(16) float sh0[HH];
    __shared__ __align__(16) float sh1[HH];
    __shared__ float shid[HU];

    const int p   = blockIdx.x;      // pair id
    const int b   = p >> 1;
    const int tid = threadIdx.x;
    const int e   = g_pair_e[p];

    // Union'd per-thread weight registers:
    //  layer-0 thread: w[0..49] = Wc row, w[50..81] = Whh0 row   (82 regs)
    //  layer-1 thread: w[0..31] = Wih1 row, w[32..63] = Whh1 row (64 regs)
    float w[FF + HH];
    float c0 = 0.f, gb = 0.f;

    if (tid < G3) {
        const int hb = horizon[b];
        const float* wc = g_Wc + (size_t)(e * G3 + tid) * FF;
#pragma unroll
        for (int f = 0; f < FF; ++f) w[f] = wc[f];
        const float* whr = Whh0 + (size_t)(e * G3 + tid) * HH;
#pragma unroll
        for (int k = 0; k < HH; ++k) w[FF + k] = whr[k];
        // bias: bih0 + Wih0_row . (b_in + emb[horizon])
        c0 = bih0[e * G3 + tid];
        const float* wi = Wih0 + (size_t)(e * G3 + tid) * DD;
        const float* hv = emb + (size_t)hb * DD;
#pragma unroll
        for (int d = 0; d < DD; ++d) c0 = fmaf(wi[d], b_in[d] + hv[d], c0);
        gb = bhh0[e * G3 + tid];
    } else {
        const int j = tid - G3;
        const float* a = Wih1 + (size_t)(e * G3 + j) * HH;
#pragma unroll
        for (int k = 0; k < HH; ++k) w[k] = a[k];
        const float* bb = Whh1 + (size_t)(e * G3 + j) * HH;
#pragma unroll
        for (int k = 0; k < HH; ++k) w[HH + k] = bb[k];
        c0 = bih1[e * G3 + j];
        gb = bhh1[e * G3 + j];
    }

    if (tid < HH)                sh0[tid] = 0.f;
    if (tid >= G3 && tid < G3 + HH) sh1[tid - G3] = 0.f;
    __syncthreads();

    const float2* xbase = (const float2*)(x + (size_t)b * LSEQ * FF);

#pragma unroll 1
    for (int it = 0; it <= LSEQ; ++it) {
        // ---- phase A: gate pre-activations --------------------------------
        if (tid < G3) {
            if (it < LSEQ) {
                const float2* xr = xbase + (size_t)it * (FF / 2);
                float a0 = c0, a1 = 0.f;
#pragma unroll
                for (int f = 0; f < FF / 2; ++f) {
                    float2 v = __ldg(xr + f);
                    a0 = fmaf(w[2 * f],     v.x, a0);
                    a1 = fmaf(w[2 * f + 1], v.y, a1);
                }
                float g = gb;
                const float4* hv = (const float4*)sh0;
#pragma unroll
                for (int k = 0; k < HH / 4; ++k) {
                    float4 h4 = hv[k];
                    g = fmaf(w[FF + 4 * k + 0], h4.x, g);
                    g = fmaf(w[FF + 4 * k + 1], h4.y, g);
                    g = fmaf(w[FF + 4 * k + 2], h4.z, g);
                    g = fmaf(w[FF + 4 * k + 3], h4.w, g);
                }
                sA0[tid] = a0 + a1;
                sG0[tid] = g;
            }
        } else {
            if (it >= 1) {              // layer 1 processes step it-1
                const int j = tid - G3;
                float a = c0, g = gb;
                const float4* h0v = (const float4*)sh0;
                const float4* h1v = (const float4*)sh1;
#pragma unroll
                for (int k = 0; k < HH / 4; ++k) {
                    float4 u = h0v[k];
                    float4 v = h1v[k];
                    a = fmaf(w[4 * k + 0], u.x, a);
                    a = fmaf(w[4 * k + 1], u.y, a);
                    a = fmaf(w[4 * k + 2], u.z, a);
                    a = fmaf(w[4 * k + 3], u.w, a);
                    g = fmaf(w[HH + 4 * k + 0], v.x, g);
                    g = fmaf(w[HH + 4 * k + 1], v.y, g);
                    g = fmaf(w[HH + 4 * k + 2], v.z, g);
                    g = fmaf(w[HH + 4 * k + 3], v.w, g);
                }
                sA1[j] = a;
                sG1[j] = g;
            }
        }
        __syncthreads();
        // ---- phase B: nonlinearity + state update -------------------------
        if (tid < HH) {
            if (it < LSEQ) {
                float r = sigm(sA0[tid]        + sG0[tid]);
                float z = sigm(sA0[HH + tid]   + sG0[HH + tid]);
                float n = tanhf(sA0[2 * HH + tid] + r * sG0[2 * HH + tid]);
                sh0[tid] = (1.f - z) * n + z * sh0[tid];
            }
        } else if (tid >= G3 && tid < G3 + HH) {
            if (it >= 1) {
                const int i = tid - G3;
                float r = sigm(sA1[i]        + sG1[i]);
                float z = sigm(sA1[HH + i]   + sG1[HH + i]);
                float n = tanhf(sA1[2 * HH + i] + r * sG1[2 * HH + i]);
                sh1[i] = (1.f - z) * n + z * sh1[i];
            }
        }
        __syncthreads();
    }

    // ---- head MLP: hid = relu(h1 @ Wh1^T + bh1); pred = hid @ Wh2^T + bh2 -
    if (tid < HU) {
        float acc = bh1[e * HU + tid];
        const float* wrow = Wh1 + (size_t)(e * HU + tid) * HH;
#pragma unroll
        for (int k = 0; k < HH; ++k) acc = fmaf(__ldg(wrow + k), sh1[k], acc);
        shid[tid] = fmaxf(acc, 0.f);
    }
    __syncthreads();
    if (tid < 32) {
        float v = shid[tid] * __ldg(Wh2 + e * HU + tid);
#pragma unroll
        for (int o = 16; o; o >>= 1) v += __shfl_xor_sync(0xffffffffu, v, o);
        if (tid == 0) g_pred[p] = v + __ldg(bh2 + e);
    }
}

// ---------------- finalize: deterministic weighted combine ----------------
__global__ void moe_finalize(float* __restrict__ out) {
    int b = threadIdx.x;
    out[b] = g_pair_w[2 * b] * g_pred[2 * b] +
             g_pair_w[2 * b + 1] * g_pred[2 * b + 1];
}

// --------------------------------------------------------------------------
extern "C" void kernel_launch(void* const* d_in, const int* in_sizes, int n_in,
                              void* d_out, int out_size) {
    (void)in_sizes; (void)n_in; (void)out_size;
    const float* x       = (const float*)d_in[0];
    const int*   horizon = (const int*)  d_in[1];
    const float* W_in    = (const float*)d_in[2];
    const float* b_in    = (const float*)d_in[3];
    const float* emb     = (const float*)d_in[4];
    const float* W_gate  = (const float*)d_in[5];
    const float* b_gate  = (const float*)d_in[6];
    const float* Wih0    = (const float*)d_in[7];
    const float* Whh0    = (const float*)d_in[8];
    const float* bih0    = (const float*)d_in[9];
    const float* bhh0    = (const float*)d_in[10];
    const float* Wih1    = (const float*)d_in[11];
    const float* Whh1    = (const float*)d_in[12];
    const float* bih1    = (const float*)d_in[13];
    const float* bhh1    = (const float*)d_in[14];
    const float* Wh1     = (const float*)d_in[15];
    const float* bh1     = (const float*)d_in[16];
    const float* Wh2     = (const float*)d_in[17];
    const float* bh2     = (const float*)d_in[18];
    float* out = (float*)d_out;

    prep_Wc<<<EE, G3>>>(Wih0, W_in);
    prep_route<<<1, BB>>>(horizon, emb, W_gate, b_gate);
    moe_gru_scan<<<2 * BB, 192>>>(x, horizon, b_in, emb,
                                  Wih0, Whh0, bih0, bhh0,
                                  Wih1, Whh1, bih1, bhh1,
                                  Wh1, bh1, Wh2, bh2);
    moe_finalize<<<1, BB>>>(out);
}

// round 5
// speedup vs baseline: 2.1968x; 2.1968x over previous
#include <cuda_runtime.h>
#include <math.h>

#define BB   256
#define LSEQ 1800
#define FF   50
#define EE   4
#define HH   32
#define DD   64
#define G3   96      // 3*H
#define HU   32

typedef unsigned long long ull;

// ---------------- device scratch (no runtime allocation allowed) ----------
__device__ float g_Wc[EE * G3 * FF];   // Wih0 @ W_in  (per expert, 96 x 50)
__device__ int   g_pair_e[2 * BB];     // routed expert per (batch, slot)
__device__ float g_pair_w[2 * BB];     // softmax weight per (batch, slot)
__device__ float g_pred[2 * BB];       // expert prediction per pair

// ---------------- packed f32x2 helpers ------------------------------------
__device__ __forceinline__ ull pk(float lo, float hi) {
    ull r; asm("mov.b64 %0, {%1, %2};" : "=l"(r) : "f"(lo), "f"(hi)); return r;
}
__device__ __forceinline__ float2 upk(ull v) {
    float2 r; asm("mov.b64 {%0, %1}, %2;" : "=f"(r.x), "=f"(r.y) : "l"(v)); return r;
}
__device__ __forceinline__ void fma2(ull& d, ull a, ull b) {
    asm("fma.rn.f32x2 %0, %1, %2, %3;" : "=l"(d) : "l"(a), "l"(b), "l"(d));
}

__device__ __forceinline__ float sigm_fast(float x) {
    return __fdividef(1.f, 1.f + __expf(-x));
}
__device__ __forceinline__ float tanh_fast(float x) {
    float e = __expf(2.f * x);                 // graceful at +/-inf
    return 1.f - __fdividef(2.f, e + 1.f);
}

// ---------------- prep: combined input weights Wc = Wih0 @ W_in -----------
__global__ void prep_Wc(const float* __restrict__ Wih0,
                        const float* __restrict__ W_in) {
    int e = blockIdx.x;          // 0..3
    int j = threadIdx.x;         // 0..95
    float wr[DD];
    const float* src = Wih0 + (size_t)(e * G3 + j) * DD;
#pragma unroll
    for (int d = 0; d < DD; ++d) wr[d] = src[d];
    float* dst = g_Wc + (size_t)(e * G3 + j) * FF;
    for (int f = 0; f < FF; ++f) {
        float s = 0.f;
#pragma unroll
        for (int d = 0; d < DD; ++d) s = fmaf(wr[d], __ldg(W_in + d * FF + f), s);
        dst[f] = s;
    }
}

// ---------------- prep: gating (top-2 of 4, softmax over top-2) -----------
__global__ void prep_route(const int* __restrict__ horizon,
                           const float* __restrict__ emb,
                           const float* __restrict__ W_gate,
                           const float* __restrict__ b_gate) {
    int b = threadIdx.x;         // 0..255
    int hb = horizon[b];
    const float* he = emb + (size_t)hb * DD;
    float lg[EE];
#pragma unroll
    for (int e = 0; e < EE; ++e) {
        float s = b_gate[e];
        const float* w = W_gate + e * DD;
#pragma unroll
        for (int d = 0; d < DD; ++d) s = fmaf(w[d], he[d], s);
        lg[e] = s;
    }
    int m1 = 0;
#pragma unroll
    for (int e = 1; e < EE; ++e) if (lg[e] > lg[m1]) m1 = e;
    int m2 = -1;
#pragma unroll
    for (int e = 0; e < EE; ++e) {
        if (e == m1) continue;
        if (m2 < 0 || lg[e] > lg[m2]) m2 = e;
    }
    float e2  = expf(lg[m2] - lg[m1]);     // <= 1
    float inv = 1.f / (1.f + e2);
    g_pair_e[2 * b]     = m1;
    g_pair_e[2 * b + 1] = m2;
    g_pair_w[2 * b]     = inv;
    g_pair_w[2 * b + 1] = e2 * inv;
}

// ---------------- main: fused 2-layer GRU scan per (batch, slot) pair -----
// 512 blocks x 384 threads, occ 2.
//   warps 0-5  (t 0..191):   layer-0 gate rows, 2 lanes per row (step t)
//   warps 6-11 (t 192..383): layer-1 gate rows, 2 lanes per row (step t-1)
//   warp 6 lanes 0..24 also prefetch x (distance-2, 4-buffer ring)
__global__ void __launch_bounds__(384, 2) moe_gru_scan(
    const float* __restrict__ x,
    const int*   __restrict__ horizon,
    const float* __restrict__ b_in,
    const float* __restrict__ emb,
    const float* __restrict__ Wih0,  const float* __restrict__ Whh0,
    const float* __restrict__ bih0,  const float* __restrict__ bhh0,
    const float* __restrict__ Wih1,  const float* __restrict__ Whh1,
    const float* __restrict__ bih1,  const float* __restrict__ bhh1,
    const float* __restrict__ Wh1,   const float* __restrict__ bh1,
    const float* __restrict__ Wh2,   const float* __restrict__ bh2)
{
    __shared__ ull  sxb[4][26];               // x ring buffers (52 floats each)
    __shared__ float sA0[G3], sG0[G3], sA1[G3], sG1[G3];
    __shared__ __align__(16) float sh0f[HH];  // layer-0 hidden (unpadded)
    __shared__ __align__(16) float sh1f[HH];  // layer-1 hidden
    __shared__ float shid[HU];

    const int p    = blockIdx.x;
    const int b    = p >> 1;
    const int t    = threadIdx.x;
    const int e    = g_pair_e[p];
    const bool lay0 = (t < 192);
    const int j    = lay0 ? (t >> 1) : ((t - 192) >> 1);
    const int half = t & 1;
    const int hbase = half * 8;               // ull offset into h arrays

    // ---- per-thread packed weights (union across layers) -----------------
    ull wA[13], wB[8];
    ull c0p = 0, gbp = 0;
#pragma unroll
    for (int i = 0; i < 13; ++i) wA[i] = 0;
#pragma unroll
    for (int i = 0; i < 8; ++i)  wB[i] = 0;

    if (lay0) {
        const ull* wc = (const ull*)(g_Wc + (size_t)(e * G3 + j) * FF);
        const ull* wh = (const ull*)(Whh0 + (size_t)(e * G3 + j) * HH);
        if (!half) {
#pragma unroll
            for (int i = 0; i < 13; ++i) wA[i] = wc[i];        // f 0..25
#pragma unroll
            for (int i = 0; i < 8; ++i)  wB[i] = wh[i];        // h 0..15
            // bias: bih0 + Wih0_row . (b_in + emb[horizon])
            const int hb = horizon[b];
            float c0 = bih0[e * G3 + j];
            const float* wi = Wih0 + (size_t)(e * G3 + j) * DD;
            const float* hv = emb + (size_t)hb * DD;
#pragma unroll
            for (int d = 0; d < DD; ++d) c0 = fmaf(wi[d], b_in[d] + hv[d], c0);
            c0p = pk(c0, 0.f);
            gbp = pk(bhh0[e * G3 + j], 0.f);
        } else {
#pragma unroll
            for (int i = 0; i < 12; ++i) wA[i] = wc[13 + i];   // f 26..49
            // wA[12] stays 0 (pairs with zeroed sxb tail slot)
#pragma unroll
            for (int i = 0; i < 8; ++i)  wB[i] = wh[8 + i];    // h 16..31
        }
    } else {
        const ull* wi = (const ull*)(Wih1 + (size_t)(e * G3 + j) * HH);
        const ull* wh = (const ull*)(Whh1 + (size_t)(e * G3 + j) * HH);
#pragma unroll
        for (int i = 0; i < 8; ++i) { wA[i] = wi[8 * half + i]; wB[i] = wh[8 * half + i]; }
        if (!half) {
            c0p = pk(bih1[e * G3 + j], 0.f);
            gbp = pk(bhh1[e * G3 + j], 0.f);
        }
    }

    // ---- shared init ------------------------------------------------------
    if (t < HH) { sh0f[t] = 0.f; sh1f[t] = 0.f; }
    if (t < 4)  sxb[t][25] = 0;               // dummy tail slot, never written
    const float2* xb2 = (const float2*)(x + (size_t)b * LSEQ * FF);
    if (t >= 192 && t < 242) {                // preload steps 0 and 1
        int q = t - 192, s = q / 25, k = q % 25;
        ((float2*)&sxb[s][0])[k] = __ldg(&xb2[s * 25 + k]);
    }
    __syncthreads();

    const int xoff = half * 13;

#pragma unroll 1
    for (int it = 0; it <= LSEQ; ++it) {
        // ---- phase A: gate pre-activations --------------------------------
        if (lay0) {
            if (it < LSEQ) {
                const ull* xb = sxb[it & 3];
                ull a2 = c0p, g2 = gbp;
#pragma unroll
                for (int i = 0; i < 13; ++i) fma2(a2, wA[i], xb[xoff + i]);
                const ull* h0 = (const ull*)sh0f;
#pragma unroll
                for (int i = 0; i < 8; ++i)  fma2(g2, wB[i], h0[hbase + i]);
                float2 ua = upk(a2), ug = upk(g2);
                float a = ua.x + ua.y, g = ug.x + ug.y;
                a += __shfl_xor_sync(0xffffffffu, a, 1);
                g += __shfl_xor_sync(0xffffffffu, g, 1);
                if (!half) { sA0[j] = a; sG0[j] = g; }
            }
        } else {
            if (it >= 1) {                    // layer 1 processes step it-1
                const ull* h0 = (const ull*)sh0f;
                const ull* h1 = (const ull*)sh1f;
                ull a2 = c0p, g2 = gbp;
#pragma unroll
                for (int i = 0; i < 8; ++i) { fma2(a2, wA[i], h0[hbase + i]);
                                              fma2(g2, wB[i], h1[hbase + i]); }
                float2 ua = upk(a2), ug = upk(g2);
                float a = ua.x + ua.y, g = ug.x + ug.y;
                a += __shfl_xor_sync(0xffffffffu, a, 1);
                g += __shfl_xor_sync(0xffffffffu, g, 1);
                if (!half) { sA1[j] = a; sG1[j] = g; }
            }
            // prefetch x[it+2] into ring (warp 6, lanes 0..24)
            int q = t - 192, s = it + 2;
            if (q < 25 && s < LSEQ)
                ((float2*)&sxb[s & 3][0])[q] = __ldg(&xb2[s * 25 + q]);
        }
        __syncthreads();
        // ---- phase B: nonlinearity + state update -------------------------
        if (t < HH) {
            if (it < LSEQ) {
                float r = sigm_fast(sA0[t]          + sG0[t]);
                float z = sigm_fast(sA0[HH + t]     + sG0[HH + t]);
                float n = tanh_fast(sA0[2 * HH + t] + r * sG0[2 * HH + t]);
                sh0f[t] = (1.f - z) * n + z * sh0f[t];
            }
        } else if (t < 2 * HH) {
            if (it >= 1) {
                int i = t - HH;
                float r = sigm_fast(sA1[i]          + sG1[i]);
                float z = sigm_fast(sA1[HH + i]     + sG1[HH + i]);
                float n = tanh_fast(sA1[2 * HH + i] + r * sG1[2 * HH + i]);
                sh1f[i] = (1.f - z) * n + z * sh1f[i];
            }
        }
        __syncthreads();
    }

    // ---- head MLP: hid = relu(h1 @ Wh1^T + bh1); pred = hid @ Wh2^T + bh2 -
    if (t < HU) {
        float acc = bh1[e * HU + t];
        const float* wr = Wh1 + (size_t)(e * HU + t) * HH;
#pragma unroll
        for (int k = 0; k < HH; ++k) acc = fmaf(__ldg(wr + k), sh1f[k], acc);
        shid[t] = fmaxf(acc, 0.f);
    }
    __syncthreads();
    if (t < 32) {
        float v = shid[t] * __ldg(Wh2 + e * HU + t);
#pragma unroll
        for (int o = 16; o; o >>= 1) v += __shfl_xor_sync(0xffffffffu, v, o);
        if (t == 0) g_pred[p] = v + __ldg(bh2 + e);
    }
}

// ---------------- finalize: deterministic weighted combine ----------------
__global__ void moe_finalize(float* __restrict__ out) {
    int b = threadIdx.x;
    out[b] = g_pair_w[2 * b] * g_pred[2 * b] +
             g_pair_w[2 * b + 1] * g_pred[2 * b + 1];
}

// --------------------------------------------------------------------------
extern "C" void kernel_launch(void* const* d_in, const int* in_sizes, int n_in,
                              void* d_out, int out_size) {
    (void)in_sizes; (void)n_in; (void)out_size;
    const float* x       = (const float*)d_in[0];
    const int*   horizon = (const int*)  d_in[1];
    const float* W_in    = (const float*)d_in[2];
    const float* b_in    = (const float*)d_in[3];
    const float* emb     = (const float*)d_in[4];
    const float* W_gate  = (const float*)d_in[5];
    const float* b_gate  = (const float*)d_in[6];
    const float* Wih0    = (const float*)d_in[7];
    const float* Whh0    = (const float*)d_in[8];
    const float* bih0    = (const float*)d_in[9];
    const float* bhh0    = (const float*)d_in[10];
    const float* Wih1    = (const float*)d_in[11];
    const float* Whh1    = (const float*)d_in[12];
    const float* bih1    = (const float*)d_in[13];
    const float* bhh1    = (const float*)d_in[14];
    const float* Wh1     = (const float*)d_in[15];
    const float* bh1     = (const float*)d_in[16];
    const float* Wh2     = (const float*)d_in[17];
    const float* bh2     = (const float*)d_in[18];
    float* out = (float*)d_out;

    prep_Wc<<<EE, G3>>>(Wih0, W_in);
    prep_route<<<1, BB>>>(horizon, emb, W_gate, b_gate);
    moe_gru_scan<<<2 * BB, 384>>>(x, horizon, b_in, emb,
                                  Wih0, Whh0, bih0, bhh0,
                                  Wih1, Whh1, bih1, bhh1,
                                  Wh1, bh1, Wh2, bh2);
    moe_finalize<<<1, BB>>>(out);
}

// round 6
// speedup vs baseline: 2.3834x; 1.0849x over previous
#include <cuda_runtime.h>
#include <math.h>

#define BB   256
#define LSEQ 1800
#define FF   50
#define EE   4
#define HH   32
#define DD   64
#define G3   96      // 3*H
#define HU   32
#define NP   (2 * BB)        // 512 routed pairs
#define LT   90              // L-steps per GEMM block (1800 / 90 = 20 chunks)

typedef unsigned long long ull;

// ---------------- device scratch (no runtime allocation allowed) ----------
__device__ float g_Wc[EE * G3 * FF];           // Wih0 @ W_in (per expert 96x50)
__device__ int   g_pair_e[NP];                  // routed expert per pair
__device__ float g_pair_w[NP];                  // softmax weight per pair
__device__ float g_pred[NP];                    // expert prediction per pair
__device__ float g_xg[(size_t)NP * LSEQ * G3];  // precomputed input gates (354MB)

// ---------------- packed f32x2 helpers ------------------------------------
__device__ __forceinline__ ull pk(float lo, float hi) {
    ull r; asm("mov.b64 %0, {%1, %2};" : "=l"(r) : "f"(lo), "f"(hi)); return r;
}
__device__ __forceinline__ float2 upk(ull v) {
    float2 r; asm("mov.b64 {%0, %1}, %2;" : "=f"(r.x), "=f"(r.y) : "l"(v)); return r;
}
__device__ __forceinline__ void fma2(ull& d, ull a, ull b) {
    asm("fma.rn.f32x2 %0, %1, %2, %3;" : "=l"(d) : "l"(a), "l"(b), "l"(d));
}

__device__ __forceinline__ float sigm_fast(float x) {
    return __fdividef(1.f, 1.f + __expf(-x));
}
__device__ __forceinline__ float tanh_fast(float x) {
    float e = __expf(2.f * x);
    return 1.f - __fdividef(2.f, e + 1.f);
}

// ---------------- prep: combined input weights Wc = Wih0 @ W_in -----------
__global__ void prep_Wc(const float* __restrict__ Wih0,
                        const float* __restrict__ W_in) {
    int e = blockIdx.x;          // 0..3
    int j = threadIdx.x;         // 0..95
    float wr[DD];
    const float* src = Wih0 + (size_t)(e * G3 + j) * DD;
#pragma unroll
    for (int d = 0; d < DD; ++d) wr[d] = src[d];
    float* dst = g_Wc + (size_t)(e * G3 + j) * FF;
    for (int f = 0; f < FF; ++f) {
        float s = 0.f;
#pragma unroll
        for (int d = 0; d < DD; ++d) s = fmaf(wr[d], __ldg(W_in + d * FF + f), s);
        dst[f] = s;
    }
}

// ---------------- prep: gating (top-2 of 4, softmax over top-2) -----------
__global__ void prep_route(const int* __restrict__ horizon,
                           const float* __restrict__ emb,
                           const float* __restrict__ W_gate,
                           const float* __restrict__ b_gate) {
    int b = threadIdx.x;         // 0..255
    int hb = horizon[b];
    const float* he = emb + (size_t)hb * DD;
    float lg[EE];
#pragma unroll
    for (int e = 0; e < EE; ++e) {
        float s = b_gate[e];
        const float* w = W_gate + e * DD;
#pragma unroll
        for (int d = 0; d < DD; ++d) s = fmaf(w[d], he[d], s);
        lg[e] = s;
    }
    int m1 = 0;
#pragma unroll
    for (int e = 1; e < EE; ++e) if (lg[e] > lg[m1]) m1 = e;
    int m2 = -1;
#pragma unroll
    for (int e = 0; e < EE; ++e) {
        if (e == m1) continue;
        if (m2 < 0 || lg[e] > lg[m2]) m2 = e;
    }
    float e2  = expf(lg[m2] - lg[m1]);     // <= 1
    float inv = 1.f / (1.f + e2);
    g_pair_e[2 * b]     = m1;
    g_pair_e[2 * b + 1] = m2;
    g_pair_w[2 * b]     = inv;
    g_pair_w[2 * b + 1] = e2 * inv;
}

// ---------------- xg GEMM: g_xg[p][l][j] = Wc[e][j].x[b][l] + c0(p,j) -----
// grid (20 chunks, 512 pairs) x 288 threads.  j = t % 96, sub = t / 96.
__global__ void __launch_bounds__(288) xg_gemm(
    const float* __restrict__ x,
    const int*   __restrict__ horizon,
    const float* __restrict__ b_in,
    const float* __restrict__ emb,
    const float* __restrict__ Wih0,
    const float* __restrict__ bih0)
{
    __shared__ __align__(16) float sx[LT * FF];   // 90 x 50 floats (17.6 KB)

    const int p  = blockIdx.y;
    const int b  = p >> 1;
    const int e  = g_pair_e[p];
    const int t  = threadIdx.x;
    const int j  = t % G3;
    const int sub = t / G3;                       // 0..2
    const int l0 = blockIdx.x * LT;

    // load x tile (contiguous 4500 floats)
    const float* xsrc = x + (size_t)b * LSEQ * FF + (size_t)l0 * FF;
    for (int i = t; i < LT * FF; i += 288) sx[i] = __ldg(xsrc + i);

    // per-thread Wc row (packed) + full fused bias c0
    ull wt[FF / 2];
    const ull* wc = (const ull*)(g_Wc + (size_t)(e * G3 + j) * FF);
#pragma unroll
    for (int i = 0; i < FF / 2; ++i) wt[i] = wc[i];

    const int hb = horizon[b];
    float c0 = bih0[e * G3 + j];
    const float* wi = Wih0 + (size_t)(e * G3 + j) * DD;
    const float* hv = emb + (size_t)hb * DD;
#pragma unroll
    for (int d = 0; d < DD; ++d) c0 = fmaf(wi[d], b_in[d] + hv[d], c0);

    __syncthreads();

    float* dst = g_xg + ((size_t)p * LSEQ + l0) * G3 + j;
#pragma unroll 1
    for (int l = sub * (LT / 3); l < (sub + 1) * (LT / 3); ++l) {
        const ull* xr = (const ull*)(sx + l * FF);
        ull acc = pk(c0, 0.f);
#pragma unroll
        for (int i = 0; i < FF / 2; ++i) fma2(acc, wt[i], xr[i]);
        float2 u = upk(acc);
        dst[(size_t)l * G3] = u.x + u.y;
    }
}

// ---------------- main: slim fused 2-layer GRU scan -----------------------
// 512 blocks x 192 threads, occ 4 -> single wave on 148 SMs.
//   threads 0..95:   layer-0 gate rows (step t); x arrives precomputed
//   threads 96..191: layer-1 gate rows (step t-1, pipelined)
__global__ void __launch_bounds__(192, 4) moe_gru_scan(
    const float* __restrict__ Whh0, const float* __restrict__ bhh0,
    const float* __restrict__ Wih1, const float* __restrict__ Whh1,
    const float* __restrict__ bih1, const float* __restrict__ bhh1,
    const float* __restrict__ Wh1,  const float* __restrict__ bh1,
    const float* __restrict__ Wh2,  const float* __restrict__ bh2)
{
    __shared__ float sA0[G3], sG0[G3], sA1[G3], sG1[G3];
    __shared__ __align__(16) float sh0f[HH];
    __shared__ __align__(16) float sh1f[HH];
    __shared__ float shid[HU];

    const int p = blockIdx.x;
    const int t = threadIdx.x;
    const int e = g_pair_e[p];
    const bool lay0 = (t < G3);
    const int j = lay0 ? t : t - G3;

    // per-thread packed recurrent weights
    ull wA[HH / 2], wB[HH / 2];
    float c0 = 0.f, gb = 0.f;
#pragma unroll
    for (int i = 0; i < HH / 2; ++i) { wA[i] = 0; wB[i] = 0; }

    const float* xgp = nullptr;
    float xcur = 0.f, xnxt = 0.f;

    if (lay0) {
        const ull* wh = (const ull*)(Whh0 + (size_t)(e * G3 + j) * HH);
#pragma unroll
        for (int i = 0; i < HH / 2; ++i) wB[i] = wh[i];
        gb = bhh0[e * G3 + j];
        xgp = g_xg + (size_t)p * LSEQ * G3 + j;
        xcur = __ldg(xgp);
        xnxt = __ldg(xgp + G3);
    } else {
        const ull* wi = (const ull*)(Wih1 + (size_t)(e * G3 + j) * HH);
        const ull* wh = (const ull*)(Whh1 + (size_t)(e * G3 + j) * HH);
#pragma unroll
        for (int i = 0; i < HH / 2; ++i) { wA[i] = wi[i]; wB[i] = wh[i]; }
        c0 = bih1[e * G3 + j];
        gb = bhh1[e * G3 + j];
    }

    if (t < HH) { sh0f[t] = 0.f; sh1f[t] = 0.f; }
    __syncthreads();

#pragma unroll 1
    for (int it = 0; it <= LSEQ; ++it) {
        // ---- phase A ------------------------------------------------------
        if (lay0) {
            // prefetch distance-2 (issue LDG before the dot product)
            float xnew = 0.f;
            if (it + 2 < LSEQ) xnew = __ldg(xgp + (size_t)(it + 2) * G3);
            if (it < LSEQ) {
                const ull* h0 = (const ull*)sh0f;
                ull g2a = pk(gb, 0.f), g2b = pk(0.f, 0.f);
#pragma unroll
                for (int i = 0; i < HH / 4; ++i) {
                    fma2(g2a, wB[2 * i],     h0[2 * i]);
                    fma2(g2b, wB[2 * i + 1], h0[2 * i + 1]);
                }
                float2 ua = upk(g2a), ub = upk(g2b);
                sA0[j] = xcur;                      // full input gate (bias folded)
                sG0[j] = (ua.x + ua.y) + (ub.x + ub.y);
            }
            xcur = xnxt; xnxt = xnew;
        } else {
            if (it >= 1) {                          // layer 1 processes step it-1
                const ull* h0 = (const ull*)sh0f;
                const ull* h1 = (const ull*)sh1f;
                ull a2a = pk(c0, 0.f), a2b = pk(0.f, 0.f);
                ull g2a = pk(gb, 0.f), g2b = pk(0.f, 0.f);
#pragma unroll
                for (int i = 0; i < HH / 4; ++i) {
                    fma2(a2a, wA[2 * i],     h0[2 * i]);
                    fma2(a2b, wA[2 * i + 1], h0[2 * i + 1]);
                    fma2(g2a, wB[2 * i],     h1[2 * i]);
                    fma2(g2b, wB[2 * i + 1], h1[2 * i + 1]);
                }
                float2 xa = upk(a2a), xb = upk(a2b), ya = upk(g2a), yb = upk(g2b);
                sA1[j] = (xa.x + xa.y) + (xb.x + xb.y);
                sG1[j] = (ya.x + ya.y) + (yb.x + yb.y);
            }
        }
        __syncthreads();
        // ---- phase B: nonlinearity + state update -------------------------
        if (t < HH) {
            if (it < LSEQ) {
                float r = sigm_fast(sA0[t]          + sG0[t]);
                float z = sigm_fast(sA0[HH + t]     + sG0[HH + t]);
                float n = tanh_fast(sA0[2 * HH + t] + r * sG0[2 * HH + t]);
                sh0f[t] = (1.f - z) * n + z * sh0f[t];
            }
        } else if (t >= G3 && t < G3 + HH) {
            if (it >= 1) {
                int i = t - G3;
                float r = sigm_fast(sA1[i]          + sG1[i]);
                float z = sigm_fast(sA1[HH + i]     + sG1[HH + i]);
                float n = tanh_fast(sA1[2 * HH + i] + r * sG1[2 * HH + i]);
                sh1f[i] = (1.f - z) * n + z * sh1f[i];
            }
        }
        __syncthreads();
    }

    // ---- head MLP: hid = relu(h1 @ Wh1^T + bh1); pred = hid @ Wh2^T + bh2 -
    if (t < HU) {
        float acc = bh1[e * HU + t];
        const float* wr = Wh1 + (size_t)(e * HU + t) * HH;
#pragma unroll
        for (int k = 0; k < HH; ++k) acc = fmaf(__ldg(wr + k), sh1f[k], acc);
        shid[t] = fmaxf(acc, 0.f);
    }
    __syncthreads();
    if (t < 32) {
        float v = shid[t] * __ldg(Wh2 + e * HU + t);
#pragma unroll
        for (int o = 16; o; o >>= 1) v += __shfl_xor_sync(0xffffffffu, v, o);
        if (t == 0) g_pred[p] = v + __ldg(bh2 + e);
    }
}

// ---------------- finalize: deterministic weighted combine ----------------
__global__ void moe_finalize(float* __restrict__ out) {
    int b = threadIdx.x;
    out[b] = g_pair_w[2 * b] * g_pred[2 * b] +
             g_pair_w[2 * b + 1] * g_pred[2 * b + 1];
}

// --------------------------------------------------------------------------
extern "C" void kernel_launch(void* const* d_in, const int* in_sizes, int n_in,
                              void* d_out, int out_size) {
    (void)in_sizes; (void)n_in; (void)out_size;
    const float* x       = (const float*)d_in[0];
    const int*   horizon = (const int*)  d_in[1];
    const float* W_in    = (const float*)d_in[2];
    const float* b_in    = (const float*)d_in[3];
    const float* emb     = (const float*)d_in[4];
    const float* W_gate  = (const float*)d_in[5];
    const float* b_gate  = (const float*)d_in[6];
    const float* Wih0    = (const float*)d_in[7];
    const float* Whh0    = (const float*)d_in[8];
    const float* bih0    = (const float*)d_in[9];
    const float* bhh0    = (const float*)d_in[10];
    const float* Wih1    = (const float*)d_in[11];
    const float* Whh1    = (const float*)d_in[12];
    const float* bih1    = (const float*)d_in[13];
    const float* bhh1    = (const float*)d_in[14];
    const float* Wh1     = (const float*)d_in[15];
    const float* bh1     = (const float*)d_in[16];
    const float* Wh2     = (const float*)d_in[17];
    const float* bh2     = (const float*)d_in[18];
    float* out = (float*)d_out;

    prep_Wc<<<EE, G3>>>(Wih0, W_in);
    prep_route<<<1, BB>>>(horizon, emb, W_gate, b_gate);
    {
        dim3 grid(LSEQ / LT, NP);
        xg_gemm<<<grid, 288>>>(x, horizon, b_in, emb, Wih0, bih0);
    }
    moe_gru_scan<<<NP, 192>>>(Whh0, bhh0, Wih1, Whh1, bih1, bhh1,
                              Wh1, bh1, Wh2, bh2);
    moe_finalize<<<1, BB>>>(out);
}